// round 1
// baseline (speedup 1.0000x reference)
#include <cuda_runtime.h>

#define T_STEPS 131072
#define IN_DIM 256
#define BN_EPS 1e-3f

// ---------------- static device scratch (no allocations allowed) ----------------
__device__ float  g_psum[256 * 256];           // partial column sums  [block][col]
__device__ float  g_psumsq[256 * 256];         // partial column sumsq [block][col]
__device__ float2 g_Wp[IN_DIM * 32];           // BN-folded W1x, paired cols (j, j+32)
__device__ float  g_biasp[64];                 // b1 + o@W1x + b3@Wh
__device__ float  g_cvec[64];                  // b3@Wh (subtracted at t=0)
__device__ float  g_Wfb[32 * 64];              // W3 @ Wh  (feedback matrix)
__device__ float2 g_V[(T_STEPS + 4) * 32];     // per-step input acts (padded for prefetch)
__device__ float  g_H2[T_STEPS * 32];          // stored 32-dim states for epilogue

// ---------------- 1) BN statistics: deterministic two-pass, pass 1 ----------------
__global__ void __launch_bounds__(256) bn_stats_kernel(const float* __restrict__ x) {
    const int c = threadIdx.x;        // column 0..255
    const int b = blockIdx.x;         // row chunk 0..255 (512 rows each)
    const float* xp = x + (size_t)b * 512 * IN_DIM + c;
    float s = 0.f, sq = 0.f;
#pragma unroll 8
    for (int r = 0; r < 512; ++r) {
        float v = xp[(size_t)r * IN_DIM];
        s += v;
        sq = fmaf(v, v, sq);
    }
    g_psum[b * 256 + c]   = s;
    g_psumsq[b * 256 + c] = sq;
}

// ---------------- 2) finalize stats + precompute folded weights ----------------
__global__ void __launch_bounds__(256) prep_kernel(
    const float* __restrict__ gamma, const float* __restrict__ beta,
    const float* __restrict__ W1,    const float* __restrict__ b1,
    const float* __restrict__ W3,    const float* __restrict__ b3)
{
    __shared__ float s_sh[256];
    __shared__ float o_sh[256];
    const int tid = threadIdx.x;

    // reduce partials for this column (deterministic order)
    {
        float s = 0.f, sq = 0.f;
#pragma unroll 8
        for (int b = 0; b < 256; ++b) {
            s  += g_psum[b * 256 + tid];
            sq += g_psumsq[b * 256 + tid];
        }
        const float invT = 1.0f / (float)T_STEPS;
        float mean = s * invT;
        float var  = fmaf(-mean, mean, sq * invT);   // E[x^2] - mean^2
        float sc   = gamma[tid] * rsqrtf(var + BN_EPS);
        s_sh[tid] = sc;
        o_sh[tid] = beta[tid] - mean * sc;
    }
    __syncthreads();

    // BN-folded W1x, stored as float2 pairs (col j, col j+32), k-major
    for (int idx = tid; idx < IN_DIM * 32; idx += 256) {
        int k = idx >> 5, j = idx & 31;
        float sc = s_sh[k];
        g_Wp[idx] = make_float2(sc * W1[k * 64 + j], sc * W1[k * 64 + j + 32]);
    }

    // feedback matrix Wfb[i][j] = sum_m W3[i][m] * Wh[m][j],  Wh = W1 rows 256..263
    for (int idx = tid; idx < 32 * 64; idx += 256) {
        int i = idx >> 6, j = idx & 63;
        float acc = 0.f;
#pragma unroll
        for (int m = 0; m < 8; ++m)
            acc = fmaf(W3[i * 8 + m], W1[(256 + m) * 64 + j], acc);
        g_Wfb[idx] = acc;
    }

    // cvec[j] = b3 @ Wh;  biasp[j] = b1[j] + o @ W1x[:,j] + cvec[j]
    if (tid < 64) {
        const int j = tid;
        float cv = 0.f;
#pragma unroll
        for (int m = 0; m < 8; ++m)
            cv = fmaf(b3[m], W1[(256 + m) * 64 + j], cv);
        float bp = b1[j] + cv;
        for (int k = 0; k < IN_DIM; ++k)
            bp = fmaf(o_sh[k], W1[k * 64 + j], bp);
        g_cvec[j]  = cv;
        g_biasp[j] = bp;
    }
}

// ---------------- 3) parallel GEMM: V[t] = xn[t] @ W1x' + biasp ----------------
__global__ void __launch_bounds__(128) vgemm_kernel(const float* __restrict__ x) {
    __shared__ float xs[4][IN_DIM];
    const int w    = threadIdx.x >> 5;
    const int lane = threadIdx.x & 31;
    const int row  = blockIdx.x * 4 + w;

    const float4* xr4 = (const float4*)(x + (size_t)row * IN_DIM);
    ((float4*)xs[w])[lane]      = xr4[lane];        // k = lane*4 .. +3
    ((float4*)xs[w])[lane + 32] = xr4[lane + 32];   // k = 128 + lane*4 ..
    __syncwarp();

    float a0 = g_biasp[lane], a1 = g_biasp[lane + 32];
    float a0b = 0.f, a1b = 0.f;
#pragma unroll 8
    for (int k = 0; k < IN_DIM; k += 2) {
        float  xk0 = xs[w][k], xk1 = xs[w][k + 1];
        float2 w0 = g_Wp[k * 32 + lane];
        float2 w1 = g_Wp[(k + 1) * 32 + lane];
        a0  = fmaf(xk0, w0.x, a0);
        a1  = fmaf(xk0, w0.y, a1);
        a0b = fmaf(xk1, w1.x, a0b);
        a1b = fmaf(xk1, w1.y, a1b);
    }
    g_V[(size_t)row * 32 + lane] = make_float2(a0 + a0b, a1 + a1b);
}

// ---------------- 4) the sequential recurrence: 1 warp, register weights ----------------
__global__ void __launch_bounds__(32, 1) seq_kernel(
    const float* __restrict__ W2, const float* __restrict__ b2)
{
    const int lane = threadIdx.x;
    const unsigned FULL = 0xffffffffu;

    // register-resident weight columns for this lane
    float wfbA[32], wfbB[32], w2a[32], w2b[32];
#pragma unroll
    for (int i = 0; i < 32; ++i) {
        wfbA[i] = g_Wfb[i * 64 + lane];
        wfbB[i] = g_Wfb[i * 64 + lane + 32];
        w2a[i]  = W2[i * 32 + lane];         // W2[c][j], c = i
        w2b[i]  = W2[(i + 32) * 32 + lane];  // c = i + 32
    }
    const float b2j = b2[lane];

    // t = 0 has no recurrent input: remove the folded b3@Wh term once
    float2 v0 = g_V[lane];
    v0.x -= g_cvec[lane];
    v0.y -= g_cvec[lane + 32];
    float2 v1 = g_V[32 + lane];

    float h2val = 0.f;

#pragma unroll 1
    for (int t = 0; t < T_STEPS; ++t) {
        float2 vpf = g_V[(size_t)(t + 2) * 32 + lane];   // prefetch (padded)

        // layer A: 64 pre-acts = V[t] + h2 @ Wfb   (broadcast h2 via shfl)
        float a00 = v0.x, a01 = 0.f, a10 = v0.y, a11 = 0.f;
#pragma unroll
        for (int i = 0; i < 32; i += 2) {
            float p = __shfl_sync(FULL, h2val, i);
            float q = __shfl_sync(FULL, h2val, i + 1);
            a00 = fmaf(p, wfbA[i],     a00);
            a01 = fmaf(q, wfbA[i + 1], a01);
            a10 = fmaf(p, wfbB[i],     a10);
            a11 = fmaf(q, wfbB[i + 1], a11);
        }
        float h1a = fmaxf(a00 + a01, 0.f);   // h1[lane]
        float h1b = fmaxf(a10 + a11, 0.f);   // h1[lane+32]

        // layer B: h2[lane] = relu(b2 + h1 @ W2[:,lane])
        float s0 = b2j, s1 = 0.f, s2 = 0.f, s3 = 0.f;
#pragma unroll
        for (int i = 0; i < 32; i += 2) {
            float pa = __shfl_sync(FULL, h1a, i);
            float qa = __shfl_sync(FULL, h1a, i + 1);
            float pb = __shfl_sync(FULL, h1b, i);
            float qb = __shfl_sync(FULL, h1b, i + 1);
            s0 = fmaf(pa, w2a[i],     s0);
            s1 = fmaf(qa, w2a[i + 1], s1);
            s2 = fmaf(pb, w2b[i],     s2);
            s3 = fmaf(qb, w2b[i + 1], s3);
        }
        h2val = fmaxf((s0 + s1) + (s2 + s3), 0.f);

        g_H2[(size_t)t * 32 + lane] = h2val;
        v0 = v1;
        v1 = vpf;
    }
}

// ---------------- 5) epilogue: out = H2 @ W3 + b3 ----------------
__global__ void __launch_bounds__(256) epi_kernel(
    const float* __restrict__ W3, const float* __restrict__ b3,
    float* __restrict__ out)
{
    const int idx = blockIdx.x * 256 + threadIdx.x;  // t*8 + m
    const int t = idx >> 3, m = idx & 7;
    const float4* h2 = (const float4*)(g_H2 + (size_t)t * 32);
    float acc = b3[m];
#pragma unroll
    for (int i4 = 0; i4 < 8; ++i4) {
        float4 h = h2[i4];
        acc = fmaf(h.x, W3[(i4 * 4 + 0) * 8 + m], acc);
        acc = fmaf(h.y, W3[(i4 * 4 + 1) * 8 + m], acc);
        acc = fmaf(h.z, W3[(i4 * 4 + 2) * 8 + m], acc);
        acc = fmaf(h.w, W3[(i4 * 4 + 3) * 8 + m], acc);
    }
    out[idx] = acc;
}

// ---------------- launch ----------------
extern "C" void kernel_launch(void* const* d_in, const int* in_sizes, int n_in,
                              void* d_out, int out_size) {
    const float* x     = (const float*)d_in[0];
    const float* gamma = (const float*)d_in[1];
    const float* beta  = (const float*)d_in[2];
    const float* W1    = (const float*)d_in[3];
    const float* b1    = (const float*)d_in[4];
    const float* W2    = (const float*)d_in[5];
    const float* b2    = (const float*)d_in[6];
    const float* W3    = (const float*)d_in[7];
    const float* b3    = (const float*)d_in[8];
    float* out = (float*)d_out;

    bn_stats_kernel<<<256, 256>>>(x);
    prep_kernel<<<1, 256>>>(gamma, beta, W1, b1, W3, b3);
    vgemm_kernel<<<T_STEPS / 4, 128>>>(x);
    seq_kernel<<<1, 32>>>(W2, b2);
    epi_kernel<<<(T_STEPS * 8) / 256, 256>>>(W3, b3, out);
}

// round 2
// speedup vs baseline: 1.2183x; 1.2183x over previous
#include <cuda_runtime.h>

#define T_STEPS 131072
#define IN_DIM 256
#define BN_EPS 1e-3f

typedef unsigned long long ull;
struct __align__(16) ull2v { ull x, y; };

// ---------------- static device scratch (no allocations allowed) ----------------
__device__ float  g_psum[256 * 256];           // partial column sums  [block][col]
__device__ float  g_psumsq[256 * 256];         // partial column sumsq [block][col]
__device__ float2 g_Wp[IN_DIM * 32];           // BN-folded W1x, paired cols (j, j+32)
__device__ float  g_biasp[64];                 // b1 + o@W1x + b3@Wh
__device__ float  g_cvec[64];                  // b3@Wh (subtracted at t=0)
__device__ float  g_Wfb[32 * 64];              // W3 @ Wh  (feedback matrix)
__device__ float2 g_V[(T_STEPS + 8) * 32];     // per-step input acts (padded for prefetch)
__device__ float  g_H2[T_STEPS * 32];          // stored 32-dim states for epilogue

// ---------------- packed f32x2 helpers ----------------
__device__ __forceinline__ ull ffma2(ull a, ull b, ull c) {
    ull d; asm("fma.rn.f32x2 %0, %1, %2, %3;" : "=l"(d) : "l"(a), "l"(b), "l"(c)); return d;
}
__device__ __forceinline__ ull add2(ull a, ull b) {
    ull d; asm("add.rn.f32x2 %0, %1, %2;" : "=l"(d) : "l"(a), "l"(b)); return d;
}
__device__ __forceinline__ ull pack2(float lo, float hi) {
    ull r; asm("mov.b64 %0, {%1, %2};" : "=l"(r) : "f"(lo), "f"(hi)); return r;
}
__device__ __forceinline__ void unpack2(ull p, float& lo, float& hi) {
    asm("mov.b64 {%0, %1}, %2;" : "=f"(lo), "=f"(hi) : "l"(p));
}

// ---------------- 1) BN statistics: deterministic two-pass, pass 1 ----------------
__global__ void __launch_bounds__(256) bn_stats_kernel(const float* __restrict__ x) {
    const int c = threadIdx.x;        // column 0..255
    const int b = blockIdx.x;         // row chunk 0..255 (512 rows each)
    const float* xp = x + (size_t)b * 512 * IN_DIM + c;
    float s = 0.f, sq = 0.f;
#pragma unroll 8
    for (int r = 0; r < 512; ++r) {
        float v = xp[(size_t)r * IN_DIM];
        s += v;
        sq = fmaf(v, v, sq);
    }
    g_psum[b * 256 + c]   = s;
    g_psumsq[b * 256 + c] = sq;
}

// ---------------- 2) finalize stats + precompute folded weights ----------------
__global__ void __launch_bounds__(256) prep_kernel(
    const float* __restrict__ gamma, const float* __restrict__ beta,
    const float* __restrict__ W1,    const float* __restrict__ b1,
    const float* __restrict__ W3,    const float* __restrict__ b3)
{
    __shared__ float s_sh[256];
    __shared__ float o_sh[256];
    const int tid = threadIdx.x;

    {
        float s = 0.f, sq = 0.f;
#pragma unroll 8
        for (int b = 0; b < 256; ++b) {
            s  += g_psum[b * 256 + tid];
            sq += g_psumsq[b * 256 + tid];
        }
        const float invT = 1.0f / (float)T_STEPS;
        float mean = s * invT;
        float var  = fmaf(-mean, mean, sq * invT);   // E[x^2] - mean^2
        float sc   = gamma[tid] * rsqrtf(var + BN_EPS);
        s_sh[tid] = sc;
        o_sh[tid] = beta[tid] - mean * sc;
    }
    __syncthreads();

    // BN-folded W1x, stored as float2 pairs (col j, col j+32), k-major
    for (int idx = tid; idx < IN_DIM * 32; idx += 256) {
        int k = idx >> 5, j = idx & 31;
        float sc = s_sh[k];
        g_Wp[idx] = make_float2(sc * W1[k * 64 + j], sc * W1[k * 64 + j + 32]);
    }

    // feedback matrix Wfb[i][j] = sum_m W3[i][m] * Wh[m][j],  Wh = W1 rows 256..263
    for (int idx = tid; idx < 32 * 64; idx += 256) {
        int i = idx >> 6, j = idx & 63;
        float acc = 0.f;
#pragma unroll
        for (int m = 0; m < 8; ++m)
            acc = fmaf(W3[i * 8 + m], W1[(256 + m) * 64 + j], acc);
        g_Wfb[idx] = acc;
    }

    // cvec[j] = b3 @ Wh;  biasp[j] = b1[j] + o @ W1x[:,j] + cvec[j]
    if (tid < 64) {
        const int j = tid;
        float cv = 0.f;
#pragma unroll
        for (int m = 0; m < 8; ++m)
            cv = fmaf(b3[m], W1[(256 + m) * 64 + j], cv);
        float bp = b1[j] + cv;
        for (int k = 0; k < IN_DIM; ++k)
            bp = fmaf(o_sh[k], W1[k * 64 + j], bp);
        g_cvec[j]  = cv;
        g_biasp[j] = bp;
    }
}

// ---------------- 3) parallel GEMM: V[t] = xn[t] @ W1x' + biasp ----------------
__global__ void __launch_bounds__(128) vgemm_kernel(const float* __restrict__ x) {
    __shared__ float xs[4][IN_DIM];
    const int w    = threadIdx.x >> 5;
    const int lane = threadIdx.x & 31;
    const int row  = blockIdx.x * 4 + w;

    const float4* xr4 = (const float4*)(x + (size_t)row * IN_DIM);
    ((float4*)xs[w])[lane]      = xr4[lane];
    ((float4*)xs[w])[lane + 32] = xr4[lane + 32];
    __syncwarp();

    float a0 = g_biasp[lane], a1 = g_biasp[lane + 32];
    float a0b = 0.f, a1b = 0.f;
#pragma unroll 8
    for (int k = 0; k < IN_DIM; k += 2) {
        float  xk0 = xs[w][k], xk1 = xs[w][k + 1];
        float2 w0 = g_Wp[k * 32 + lane];
        float2 w1 = g_Wp[(k + 1) * 32 + lane];
        a0  = fmaf(xk0, w0.x, a0);
        a1  = fmaf(xk0, w0.y, a1);
        a0b = fmaf(xk1, w1.x, a0b);
        a1b = fmaf(xk1, w1.y, a1b);
    }
    g_V[(size_t)row * 32 + lane] = make_float2(a0 + a0b, a1 + a1b);
}

// ---------------- 4) sequential recurrence: 1 warp, smem broadcast + f32x2 FMA ----------------
__global__ void __launch_bounds__(32, 1) seq_kernel(
    const float* __restrict__ W2, const float* __restrict__ b2)
{
    // sh_h2[i] holds (h2[i], h2[i]) duplicated; sh_h1[i] holds (h1[i], h1[i+32])
    __shared__ __align__(16) float2 sh_h2[32];
    __shared__ __align__(16) float2 sh_h1[32];

    const int lane = threadIdx.x;

    // packed register-resident weights
    ull wfb[32];   // (Wfb[i][lane], Wfb[i][lane+32])
    ull w2p[32];   // (W2[i][lane],  W2[i+32][lane])
#pragma unroll
    for (int i = 0; i < 32; ++i) {
        wfb[i] = pack2(g_Wfb[i * 64 + lane], g_Wfb[i * 64 + lane + 32]);
        w2p[i] = pack2(W2[i * 32 + lane],    W2[(i + 32) * 32 + lane]);
    }
    const float b2j = b2[lane];

    const ull* __restrict__ gv = (const ull*)g_V;

    // t = 0: no recurrent input — remove the folded b3@Wh term once
    float2 v0f = g_V[lane];
    v0f.x -= g_cvec[lane];
    v0f.y -= g_cvec[lane + 32];
    ull v0 = pack2(v0f.x, v0f.y);
    ull v1 = gv[32 + lane];
    ull v2 = gv[64 + lane];

    sh_h2[lane] = make_float2(0.f, 0.f);
    __syncthreads();

    const ull2v* __restrict__ h2q = (const ull2v*)sh_h2;
    const ull2v* __restrict__ h1q = (const ull2v*)sh_h1;

#pragma unroll 1
    for (int t = 0; t < T_STEPS; ++t) {
        ull vpf = gv[(size_t)(t + 3) * 32 + lane];   // prefetch depth 3 (padded)

        // ---- layer A: h1 pair = relu(V[t] + h2 @ Wfb) ----
        ull a0 = v0, a1 = 0ull, a2 = 0ull, a3 = 0ull;
#pragma unroll
        for (int m = 0; m < 16; ++m) {
            ull2v q = h2q[m];                 // ((h2[2m],h2[2m]), (h2[2m+1],h2[2m+1]))
            if ((m & 1) == 0) {
                a0 = ffma2(q.x, wfb[2 * m],     a0);
                a1 = ffma2(q.y, wfb[2 * m + 1], a1);
            } else {
                a2 = ffma2(q.x, wfb[2 * m],     a2);
                a3 = ffma2(q.y, wfb[2 * m + 1], a3);
            }
        }
        ull sA = add2(add2(a0, a2), add2(a1, a3));
        float h1a, h1b; unpack2(sA, h1a, h1b);
        h1a = fmaxf(h1a, 0.f);
        h1b = fmaxf(h1b, 0.f);
        sh_h1[lane] = make_float2(h1a, h1b);  // = (h1[lane], h1[lane+32])
        __syncthreads();

        // ---- layer B: h2[lane] = relu(b2 + h1 @ W2[:,lane]) ----
        ull s0 = 0ull, s1 = 0ull, s2 = 0ull, s3 = 0ull;
#pragma unroll
        for (int m = 0; m < 16; ++m) {
            ull2v q = h1q[m];                 // ((h1[2m],h1[2m+32]), (h1[2m+1],h1[2m+33]))
            if ((m & 1) == 0) {
                s0 = ffma2(q.x, w2p[2 * m],     s0);
                s1 = ffma2(q.y, w2p[2 * m + 1], s1);
            } else {
                s2 = ffma2(q.x, w2p[2 * m],     s2);
                s3 = ffma2(q.y, w2p[2 * m + 1], s3);
            }
        }
        ull sB = add2(add2(s0, s2), add2(s1, s3));
        float xlo, xhi; unpack2(sB, xlo, xhi);
        float h2v = fmaxf((xlo + xhi) + b2j, 0.f);

        g_H2[(size_t)t * 32 + lane] = h2v;
        sh_h2[lane] = make_float2(h2v, h2v);
        __syncthreads();

        v0 = v1; v1 = v2; v2 = vpf;
    }
}

// ---------------- 5) epilogue: out = H2 @ W3 + b3 ----------------
__global__ void __launch_bounds__(256) epi_kernel(
    const float* __restrict__ W3, const float* __restrict__ b3,
    float* __restrict__ out)
{
    const int idx = blockIdx.x * 256 + threadIdx.x;  // t*8 + m
    const int t = idx >> 3, m = idx & 7;
    const float4* h2 = (const float4*)(g_H2 + (size_t)t * 32);
    float acc = b3[m];
#pragma unroll
    for (int i4 = 0; i4 < 8; ++i4) {
        float4 h = h2[i4];
        acc = fmaf(h.x, W3[(i4 * 4 + 0) * 8 + m], acc);
        acc = fmaf(h.y, W3[(i4 * 4 + 1) * 8 + m], acc);
        acc = fmaf(h.z, W3[(i4 * 4 + 2) * 8 + m], acc);
        acc = fmaf(h.w, W3[(i4 * 4 + 3) * 8 + m], acc);
    }
    out[idx] = acc;
}

// ---------------- launch ----------------
extern "C" void kernel_launch(void* const* d_in, const int* in_sizes, int n_in,
                              void* d_out, int out_size) {
    const float* x     = (const float*)d_in[0];
    const float* gamma = (const float*)d_in[1];
    const float* beta  = (const float*)d_in[2];
    const float* W1    = (const float*)d_in[3];
    const float* b1    = (const float*)d_in[4];
    const float* W2    = (const float*)d_in[5];
    const float* b2    = (const float*)d_in[6];
    const float* W3    = (const float*)d_in[7];
    const float* b3    = (const float*)d_in[8];
    float* out = (float*)d_out;

    bn_stats_kernel<<<256, 256>>>(x);
    prep_kernel<<<1, 256>>>(gamma, beta, W1, b1, W3, b3);
    vgemm_kernel<<<T_STEPS / 4, 128>>>(x);
    seq_kernel<<<1, 32>>>(W2, b2);
    epi_kernel<<<(T_STEPS * 8) / 256, 256>>>(W3, b3, out);
}

// round 3
// speedup vs baseline: 1.7994x; 1.4770x over previous
#include <cuda_runtime.h>

#define T_STEPS 131072
#define IN_DIM 256
#define BN_EPS 1e-3f

typedef unsigned long long ull;
struct __align__(16) ull2v { ull x, y; };

// ---------------- static device scratch (no allocations allowed) ----------------
__device__ float  g_psum[256 * 256];           // partial column sums  [block][col]
__device__ float  g_psumsq[256 * 256];         // partial column sumsq [block][col]
__device__ float2 g_Wp[IN_DIM * 32];           // BN-folded W1x, paired cols (j, j+32)
__device__ float  g_biasp[64];                 // b1 + o@W1x + b3@Wh
__device__ float  g_cvec[64];                  // b3@Wh (subtracted at t=0)
__device__ float  g_Wfb[32 * 64];              // W3 @ Wh  (feedback matrix)
__device__ float2 g_V[(T_STEPS + 16) * 32];    // per-step input acts (padded for prefetch)
__device__ float  g_H2[T_STEPS * 32];          // stored 32-dim states for epilogue

// ---------------- packed f32x2 helpers ----------------
__device__ __forceinline__ ull ffma2(ull a, ull b, ull c) {
    ull d; asm("fma.rn.f32x2 %0, %1, %2, %3;" : "=l"(d) : "l"(a), "l"(b), "l"(c)); return d;
}
__device__ __forceinline__ ull add2(ull a, ull b) {
    ull d; asm("add.rn.f32x2 %0, %1, %2;" : "=l"(d) : "l"(a), "l"(b)); return d;
}
__device__ __forceinline__ ull pack2(float lo, float hi) {
    ull r; asm("mov.b64 %0, {%1, %2};" : "=l"(r) : "f"(lo), "f"(hi)); return r;
}
__device__ __forceinline__ void unpack2(ull p, float& lo, float& hi) {
    asm("mov.b64 {%0, %1}, %2;" : "=f"(lo), "=f"(hi) : "l"(p));
}

// ---------------- 1) BN statistics: deterministic two-pass, pass 1 ----------------
__global__ void __launch_bounds__(256) bn_stats_kernel(const float* __restrict__ x) {
    const int c = threadIdx.x;        // column 0..255
    const int b = blockIdx.x;         // row chunk 0..255 (512 rows each)
    const float* xp = x + (size_t)b * 512 * IN_DIM + c;
    float s = 0.f, sq = 0.f;
#pragma unroll 8
    for (int r = 0; r < 512; ++r) {
        float v = xp[(size_t)r * IN_DIM];
        s += v;
        sq = fmaf(v, v, sq);
    }
    g_psum[b * 256 + c]   = s;
    g_psumsq[b * 256 + c] = sq;
}

// ---------------- 2) finalize stats + precompute folded weights ----------------
__global__ void __launch_bounds__(256) prep_kernel(
    const float* __restrict__ gamma, const float* __restrict__ beta,
    const float* __restrict__ W1,    const float* __restrict__ b1,
    const float* __restrict__ W3,    const float* __restrict__ b3)
{
    __shared__ float s_sh[256];
    __shared__ float o_sh[256];
    const int tid = threadIdx.x;

    {
        float s = 0.f, sq = 0.f;
#pragma unroll 8
        for (int b = 0; b < 256; ++b) {
            s  += g_psum[b * 256 + tid];
            sq += g_psumsq[b * 256 + tid];
        }
        const float invT = 1.0f / (float)T_STEPS;
        float mean = s * invT;
        float var  = fmaf(-mean, mean, sq * invT);   // E[x^2] - mean^2
        float sc   = gamma[tid] * rsqrtf(var + BN_EPS);
        s_sh[tid] = sc;
        o_sh[tid] = beta[tid] - mean * sc;
    }
    __syncthreads();

    // BN-folded W1x, stored as float2 pairs (col j, col j+32), k-major
    for (int idx = tid; idx < IN_DIM * 32; idx += 256) {
        int k = idx >> 5, j = idx & 31;
        float sc = s_sh[k];
        g_Wp[idx] = make_float2(sc * W1[k * 64 + j], sc * W1[k * 64 + j + 32]);
    }

    // feedback matrix Wfb[i][j] = sum_m W3[i][m] * Wh[m][j],  Wh = W1 rows 256..263
    for (int idx = tid; idx < 32 * 64; idx += 256) {
        int i = idx >> 6, j = idx & 63;
        float acc = 0.f;
#pragma unroll
        for (int m = 0; m < 8; ++m)
            acc = fmaf(W3[i * 8 + m], W1[(256 + m) * 64 + j], acc);
        g_Wfb[idx] = acc;
    }

    // cvec[j] = b3 @ Wh;  biasp[j] = b1[j] + o @ W1x[:,j] + cvec[j]
    if (tid < 64) {
        const int j = tid;
        float cv = 0.f;
#pragma unroll
        for (int m = 0; m < 8; ++m)
            cv = fmaf(b3[m], W1[(256 + m) * 64 + j], cv);
        float bp = b1[j] + cv;
        for (int k = 0; k < IN_DIM; ++k)
            bp = fmaf(o_sh[k], W1[k * 64 + j], bp);
        g_cvec[j]  = cv;
        g_biasp[j] = bp;
    }
}

// ---------------- 3) parallel GEMM: V[t] = xn[t] @ W1x' + biasp ----------------
__global__ void __launch_bounds__(128) vgemm_kernel(const float* __restrict__ x) {
    __shared__ float xs[4][IN_DIM];
    const int w    = threadIdx.x >> 5;
    const int lane = threadIdx.x & 31;
    const int row  = blockIdx.x * 4 + w;

    const float4* xr4 = (const float4*)(x + (size_t)row * IN_DIM);
    ((float4*)xs[w])[lane]      = xr4[lane];
    ((float4*)xs[w])[lane + 32] = xr4[lane + 32];
    __syncwarp();

    float a0 = g_biasp[lane], a1 = g_biasp[lane + 32];
    float a0b = 0.f, a1b = 0.f;
#pragma unroll 8
    for (int k = 0; k < IN_DIM; k += 2) {
        float  xk0 = xs[w][k], xk1 = xs[w][k + 1];
        float2 w0 = g_Wp[k * 32 + lane];
        float2 w1 = g_Wp[(k + 1) * 32 + lane];
        a0  = fmaf(xk0, w0.x, a0);
        a1  = fmaf(xk0, w0.y, a1);
        a0b = fmaf(xk1, w1.x, a0b);
        a1b = fmaf(xk1, w1.y, a1b);
    }
    g_V[(size_t)row * 32 + lane] = make_float2(a0 + a0b, a1 + a1b);
}

// ---------------- 4) sequential recurrence: 1 warp, syncwarp + 8-acc f32x2 ----------------
__global__ void __launch_bounds__(32, 1) seq_kernel(
    const float* __restrict__ W2, const float* __restrict__ b2)
{
    // sh_h2[i] = (h2[i], h2[i]) duplicated; sh_h1[i] = (h1[i], h1[i+32])
    __shared__ __align__(16) float2 sh_h2[32];
    __shared__ __align__(16) float2 sh_h1[32];

    const int lane = threadIdx.x;

    ull wfb[32];   // (Wfb[i][lane], Wfb[i][lane+32])
    ull w2p[32];   // (W2[i][lane],  W2[i+32][lane])
#pragma unroll
    for (int i = 0; i < 32; ++i) {
        wfb[i] = pack2(g_Wfb[i * 64 + lane], g_Wfb[i * 64 + lane + 32]);
        w2p[i] = pack2(W2[i * 32 + lane],    W2[(i + 32) * 32 + lane]);
    }
    const ull b2p = pack2(b2[lane], 0.f);

    const ull* __restrict__ gv = (const ull*)g_V;

    // t = 0: no recurrent input — remove the folded b3@Wh term once
    float2 v0f = g_V[lane];
    v0f.x -= g_cvec[lane];
    v0f.y -= g_cvec[lane + 32];
    ull vr0 = pack2(v0f.x, v0f.y);
    ull vr1 = gv[32 + lane];
    ull vr2 = gv[64 + lane];
    ull vr3 = gv[96 + lane];

    sh_h2[lane] = make_float2(0.f, 0.f);
    __syncwarp();

    const ull2v* __restrict__ h2q = (const ull2v*)sh_h2;
    const ull2v* __restrict__ h1q = (const ull2v*)sh_h1;

#define SEQ_STEP(VREG, TT)                                                     \
    do {                                                                       \
        /* ---- layer A: h1 pair = relu(V + h2 @ Wfb) ---- */                  \
        ull a[8];                                                              \
        a[0] = VREG; a[1] = 0; a[2] = 0; a[3] = 0;                             \
        a[4] = 0;    a[5] = 0; a[6] = 0; a[7] = 0;                             \
        _Pragma("unroll")                                                      \
        for (int m = 0; m < 16; ++m) {                                         \
            ull2v q = h2q[m];                                                  \
            a[(2 * m) & 7]     = ffma2(q.x, wfb[2 * m],     a[(2 * m) & 7]);   \
            a[(2 * m + 1) & 7] = ffma2(q.y, wfb[2 * m + 1], a[(2 * m + 1) & 7]); \
        }                                                                      \
        VREG = gv[(size_t)((TT) + 4) * 32 + lane];  /* in-place prefetch */    \
        ull sA = add2(add2(add2(a[0], a[2]), add2(a[4], a[6])),                \
                      add2(add2(a[1], a[3]), add2(a[5], a[7])));               \
        float h1a, h1b; unpack2(sA, h1a, h1b);                                 \
        h1a = fmaxf(h1a, 0.f);                                                 \
        h1b = fmaxf(h1b, 0.f);                                                 \
        sh_h1[lane] = make_float2(h1a, h1b);                                   \
        __syncwarp();                                                          \
        /* ---- layer B: h2 = relu(b2 + h1 @ W2) ---- */                       \
        ull s[8];                                                              \
        s[0] = b2p; s[1] = 0; s[2] = 0; s[3] = 0;                              \
        s[4] = 0;   s[5] = 0; s[6] = 0; s[7] = 0;                              \
        _Pragma("unroll")                                                      \
        for (int m = 0; m < 16; ++m) {                                         \
            ull2v q = h1q[m];                                                  \
            s[(2 * m) & 7]     = ffma2(q.x, w2p[2 * m],     s[(2 * m) & 7]);   \
            s[(2 * m + 1) & 7] = ffma2(q.y, w2p[2 * m + 1], s[(2 * m + 1) & 7]); \
        }                                                                      \
        ull sB = add2(add2(add2(s[0], s[2]), add2(s[4], s[6])),                \
                      add2(add2(s[1], s[3]), add2(s[5], s[7])));               \
        float xlo, xhi; unpack2(sB, xlo, xhi);                                 \
        float h2v = fmaxf(xlo + xhi, 0.f);                                     \
        g_H2[(size_t)(TT) * 32 + lane] = h2v;                                  \
        sh_h2[lane] = make_float2(h2v, h2v);                                   \
        __syncwarp();                                                          \
    } while (0)

#pragma unroll 1
    for (int t = 0; t < T_STEPS; t += 4) {
        SEQ_STEP(vr0, t + 0);
        SEQ_STEP(vr1, t + 1);
        SEQ_STEP(vr2, t + 2);
        SEQ_STEP(vr3, t + 3);
    }
#undef SEQ_STEP
}

// ---------------- 5) epilogue: out = H2 @ W3 + b3 ----------------
__global__ void __launch_bounds__(256) epi_kernel(
    const float* __restrict__ W3, const float* __restrict__ b3,
    float* __restrict__ out)
{
    const int idx = blockIdx.x * 256 + threadIdx.x;  // t*8 + m
    const int t = idx >> 3, m = idx & 7;
    const float4* h2 = (const float4*)(g_H2 + (size_t)t * 32);
    float acc = b3[m];
#pragma unroll
    for (int i4 = 0; i4 < 8; ++i4) {
        float4 h = h2[i4];
        acc = fmaf(h.x, W3[(i4 * 4 + 0) * 8 + m], acc);
        acc = fmaf(h.y, W3[(i4 * 4 + 1) * 8 + m], acc);
        acc = fmaf(h.z, W3[(i4 * 4 + 2) * 8 + m], acc);
        acc = fmaf(h.w, W3[(i4 * 4 + 3) * 8 + m], acc);
    }
    out[idx] = acc;
}

// ---------------- launch ----------------
extern "C" void kernel_launch(void* const* d_in, const int* in_sizes, int n_in,
                              void* d_out, int out_size) {
    const float* x     = (const float*)d_in[0];
    const float* gamma = (const float*)d_in[1];
    const float* beta  = (const float*)d_in[2];
    const float* W1    = (const float*)d_in[3];
    const float* b1    = (const float*)d_in[4];
    const float* W2    = (const float*)d_in[5];
    const float* b2    = (const float*)d_in[6];
    const float* W3    = (const float*)d_in[7];
    const float* b3    = (const float*)d_in[8];
    float* out = (float*)d_out;

    bn_stats_kernel<<<256, 256>>>(x);
    prep_kernel<<<1, 256>>>(gamma, beta, W1, b1, W3, b3);
    vgemm_kernel<<<T_STEPS / 4, 128>>>(x);
    seq_kernel<<<1, 32>>>(W2, b2);
    epi_kernel<<<(T_STEPS * 8) / 256, 256>>>(W3, b3, out);
}

// round 5
// speedup vs baseline: 1.9029x; 1.0575x over previous
#include <cuda_runtime.h>

#define T_STEPS 131072
#define IN_DIM 256
#define BN_EPS 1e-3f

typedef unsigned long long ull;
struct __align__(16) ull2v { ull x, y; };

// ---------------- static device scratch (no allocations allowed) ----------------
__device__ float  g_psum[256 * 256];           // partial column sums  [block][col]
__device__ float  g_psumsq[256 * 256];         // partial column sumsq [block][col]
__device__ float2 g_Wp[IN_DIM * 32];           // BN-folded W1x, paired cols (j, j+32)
__device__ float  g_biasp[64];                 // b1 + o@W1x + b3@Wh
__device__ float  g_cvec[64];                  // b3@Wh (subtracted at t=0)
__device__ float  g_Wfb[32 * 64];              // W3 @ Wh  (feedback matrix)
__device__ float2 g_V[(T_STEPS + 16) * 32];    // per-step input acts (padded for prefetch)
__device__ float  g_H2[T_STEPS * 32];          // stored 32-dim states for epilogue

// ---------------- packed f32x2 helpers ----------------
__device__ __forceinline__ ull ffma2(ull a, ull b, ull c) {
    ull d; asm("fma.rn.f32x2 %0, %1, %2, %3;" : "=l"(d) : "l"(a), "l"(b), "l"(c)); return d;
}
__device__ __forceinline__ ull add2(ull a, ull b) {
    ull d; asm("add.rn.f32x2 %0, %1, %2;" : "=l"(d) : "l"(a), "l"(b)); return d;
}
__device__ __forceinline__ ull pack2(float lo, float hi) {
    ull r; asm("mov.b64 %0, {%1, %2};" : "=l"(r) : "f"(lo), "f"(hi)); return r;
}
__device__ __forceinline__ void unpack2(ull p, float& lo, float& hi) {
    asm("mov.b64 {%0, %1}, %2;" : "=f"(lo), "=f"(hi) : "l"(p));
}
__device__ __forceinline__ ull relu2(ull p) {
    float lo, hi; unpack2(p, lo, hi);
    return pack2(fmaxf(lo, 0.f), fmaxf(hi, 0.f));
}

// ---------------- 1) BN statistics: deterministic two-pass, pass 1 ----------------
__global__ void __launch_bounds__(256) bn_stats_kernel(const float* __restrict__ x) {
    const int c = threadIdx.x;        // column 0..255
    const int b = blockIdx.x;         // row chunk 0..255 (512 rows each)
    const float* xp = x + (size_t)b * 512 * IN_DIM + c;
    float s = 0.f, sq = 0.f;
#pragma unroll 8
    for (int r = 0; r < 512; ++r) {
        float v = xp[(size_t)r * IN_DIM];
        s += v;
        sq = fmaf(v, v, sq);
    }
    g_psum[b * 256 + c]   = s;
    g_psumsq[b * 256 + c] = sq;
}

// ---------------- 2) finalize stats + precompute folded weights ----------------
__global__ void __launch_bounds__(256) prep_kernel(
    const float* __restrict__ gamma, const float* __restrict__ beta,
    const float* __restrict__ W1,    const float* __restrict__ b1,
    const float* __restrict__ W3,    const float* __restrict__ b3)
{
    __shared__ float s_sh[256];
    __shared__ float o_sh[256];
    const int tid = threadIdx.x;

    {
        float s = 0.f, sq = 0.f;
#pragma unroll 8
        for (int b = 0; b < 256; ++b) {
            s  += g_psum[b * 256 + tid];
            sq += g_psumsq[b * 256 + tid];
        }
        const float invT = 1.0f / (float)T_STEPS;
        float mean = s * invT;
        float var  = fmaf(-mean, mean, sq * invT);   // E[x^2] - mean^2
        float sc   = gamma[tid] * rsqrtf(var + BN_EPS);
        s_sh[tid] = sc;
        o_sh[tid] = beta[tid] - mean * sc;
    }
    __syncthreads();

    // BN-folded W1x, stored as float2 pairs (col j, col j+32), k-major
    for (int idx = tid; idx < IN_DIM * 32; idx += 256) {
        int k = idx >> 5, j = idx & 31;
        float sc = s_sh[k];
        g_Wp[idx] = make_float2(sc * W1[k * 64 + j], sc * W1[k * 64 + j + 32]);
    }

    // feedback matrix Wfb[i][j] = sum_m W3[i][m] * Wh[m][j],  Wh = W1 rows 256..263
    for (int idx = tid; idx < 32 * 64; idx += 256) {
        int i = idx >> 6, j = idx & 63;
        float acc = 0.f;
#pragma unroll
        for (int m = 0; m < 8; ++m)
            acc = fmaf(W3[i * 8 + m], W1[(256 + m) * 64 + j], acc);
        g_Wfb[idx] = acc;
    }

    // cvec[j] = b3 @ Wh;  biasp[j] = b1[j] + o @ W1x[:,j] + cvec[j]
    if (tid < 64) {
        const int j = tid;
        float cv = 0.f;
#pragma unroll
        for (int m = 0; m < 8; ++m)
            cv = fmaf(b3[m], W1[(256 + m) * 64 + j], cv);
        float bp = b1[j] + cv;
        for (int k = 0; k < IN_DIM; ++k)
            bp = fmaf(o_sh[k], W1[k * 64 + j], bp);
        g_cvec[j]  = cv;
        g_biasp[j] = bp;
    }
}

// ---------------- 3) parallel GEMM: V[t] = xn[t] @ W1x' + biasp ----------------
__global__ void __launch_bounds__(128) vgemm_kernel(const float* __restrict__ x) {
    __shared__ float xs[4][IN_DIM];
    const int w    = threadIdx.x >> 5;
    const int lane = threadIdx.x & 31;
    const int row  = blockIdx.x * 4 + w;

    const float4* xr4 = (const float4*)(x + (size_t)row * IN_DIM);
    ((float4*)xs[w])[lane]      = xr4[lane];
    ((float4*)xs[w])[lane + 32] = xr4[lane + 32];
    __syncwarp();

    float a0 = g_biasp[lane], a1 = g_biasp[lane + 32];
    float a0b = 0.f, a1b = 0.f;
#pragma unroll 8
    for (int k = 0; k < IN_DIM; k += 2) {
        float  xk0 = xs[w][k], xk1 = xs[w][k + 1];
        float2 w0 = g_Wp[k * 32 + lane];
        float2 w1 = g_Wp[(k + 1) * 32 + lane];
        a0  = fmaf(xk0, w0.x, a0);
        a1  = fmaf(xk0, w0.y, a1);
        a0b = fmaf(xk1, w1.x, a0b);
        a1b = fmaf(xk1, w1.y, a1b);
    }
    g_V[(size_t)row * 32 + lane] = make_float2(a0 + a0b, a1 + a1b);
}

// ---------------- 4) sequential recurrence: 1 warp, sync-free smem exchange ----------------
__global__ void __launch_bounds__(32, 1) seq_kernel(
    const float* __restrict__ W2, const float* __restrict__ b2)
{
    // sh_h2[i] = (h2[i], h2[i]) duplicated; sh_h1[i] = (h1[i], h1[i+32])
    __shared__ __align__(16) ull sh_h2[32];
    __shared__ __align__(16) ull sh_h1[32];

    const int lane = threadIdx.x;

    ull wfb[32];   // (Wfb[i][lane], Wfb[i][lane+32])
    ull w2p[32];   // (W2[i][lane],  W2[i+32][lane])
#pragma unroll
    for (int i = 0; i < 32; ++i) {
        wfb[i] = pack2(g_Wfb[i * 64 + lane], g_Wfb[i * 64 + lane + 32]);
        w2p[i] = pack2(W2[i * 32 + lane],    W2[(i + 32) * 32 + lane]);
    }
    const ull b2p = pack2(b2[lane], 0.f);

    const ull* __restrict__ gv = (const ull*)g_V;

    // t = 0: no recurrent input — remove the folded b3@Wh term once
    float2 v0f = g_V[lane];
    v0f.x -= g_cvec[lane];
    v0f.y -= g_cvec[lane + 32];
    ull vr0 = pack2(v0f.x, v0f.y);
    ull vr1 = gv[32 + lane];
    ull vr2 = gv[64 + lane];
    ull vr3 = gv[96 + lane];

    sh_h2[lane] = 0ull;
    __syncwarp();

    const ull2v* __restrict__ h2q = (const ull2v*)sh_h2;
    const ull2v* __restrict__ h1q = (const ull2v*)sh_h1;

    const ull*   pv = gv + 4 * 32 + lane;   // prefetch pointer (t+4)
    float*       ph = g_H2 + lane;          // h2 history pointer

#define CBAR() asm volatile("" ::: "memory")

#define SEQ_STEP(VREG, OFF)                                                    \
    do {                                                                       \
        /* ---- layer A: h1 pair = relu(V + h2 @ Wfb) ---- */                  \
        ull a[8];                                                              \
        a[0] = VREG; a[1] = 0; a[2] = 0; a[3] = 0;                             \
        a[4] = 0;    a[5] = 0; a[6] = 0; a[7] = 0;                             \
        _Pragma("unroll")                                                      \
        for (int m = 0; m < 16; ++m) {                                         \
            ull2v q = h2q[m];                                                  \
            a[(2 * m) & 7]     = ffma2(q.x, wfb[2 * m],     a[(2 * m) & 7]);   \
            a[(2 * m + 1) & 7] = ffma2(q.y, wfb[2 * m + 1], a[(2 * m + 1) & 7]); \
        }                                                                      \
        ull sA = add2(add2(add2(a[0], a[2]), add2(a[4], a[6])),                \
                      add2(add2(a[1], a[3]), add2(a[5], a[7])));               \
        sh_h1[lane] = relu2(sA);                                               \
        CBAR();                                                                \
        VREG = pv[(OFF) * 32];           /* spacing: independent LDG */        \
        CBAR();                                                                \
        /* ---- layer B: h2 = relu(b2 + h1 @ W2) ---- */                       \
        ull s[8];                                                              \
        s[0] = b2p; s[1] = 0; s[2] = 0; s[3] = 0;                              \
        s[4] = 0;   s[5] = 0; s[6] = 0; s[7] = 0;                              \
        _Pragma("unroll")                                                      \
        for (int m = 0; m < 16; ++m) {                                         \
            ull2v q = h1q[m];                                                  \
            s[(2 * m) & 7]     = ffma2(q.x, w2p[2 * m],     s[(2 * m) & 7]);   \
            s[(2 * m + 1) & 7] = ffma2(q.y, w2p[2 * m + 1], s[(2 * m + 1) & 7]); \
        }                                                                      \
        ull sB = add2(add2(add2(s[0], s[2]), add2(s[4], s[6])),                \
                      add2(add2(s[1], s[3]), add2(s[5], s[7])));               \
        float xlo, xhi; unpack2(sB, xlo, xhi);                                 \
        float h2v = fmaxf(xlo + xhi, 0.f);                                     \
        sh_h2[lane] = pack2(h2v, h2v);                                         \
        CBAR();                                                                \
        ph[(OFF) * 32] = h2v;            /* spacing: independent STG */        \
        CBAR();                                                                \
    } while (0)

#pragma unroll 1
    for (int t = 0; t < T_STEPS; t += 4) {
        SEQ_STEP(vr0, 0);
        SEQ_STEP(vr1, 1);
        SEQ_STEP(vr2, 2);
        SEQ_STEP(vr3, 3);
        pv += 128;
        ph += 128;
    }
#undef SEQ_STEP
#undef CBAR
}

// ---------------- 5) epilogue: out = H2 @ W3 + b3 ----------------
__global__ void __launch_bounds__(256) epi_kernel(
    const float* __restrict__ W3, const float* __restrict__ b3,
    float* __restrict__ out)
{
    const int idx = blockIdx.x * 256 + threadIdx.x;  // t*8 + m
    const int t = idx >> 3, m = idx & 7;
    const float4* h2 = (const float4*)(g_H2 + (size_t)t * 32);
    float acc = b3[m];
#pragma unroll
    for (int i4 = 0; i4 < 8; ++i4) {
        float4 h = h2[i4];
        acc = fmaf(h.x, W3[(i4 * 4 + 0) * 8 + m], acc);
        acc = fmaf(h.y, W3[(i4 * 4 + 1) * 8 + m], acc);
        acc = fmaf(h.z, W3[(i4 * 4 + 2) * 8 + m], acc);
        acc = fmaf(h.w, W3[(i4 * 4 + 3) * 8 + m], acc);
    }
    out[idx] = acc;
}

// ---------------- launch ----------------
extern "C" void kernel_launch(void* const* d_in, const int* in_sizes, int n_in,
                              void* d_out, int out_size) {
    const float* x     = (const float*)d_in[0];
    const float* gamma = (const float*)d_in[1];
    const float* beta  = (const float*)d_in[2];
    const float* W1    = (const float*)d_in[3];
    const float* b1    = (const float*)d_in[4];
    const float* W2    = (const float*)d_in[5];
    const float* b2    = (const float*)d_in[6];
    const float* W3    = (const float*)d_in[7];
    const float* b3    = (const float*)d_in[8];
    float* out = (float*)d_out;

    bn_stats_kernel<<<256, 256>>>(x);
    prep_kernel<<<1, 256>>>(gamma, beta, W1, b1, W3, b3);
    vgemm_kernel<<<T_STEPS / 4, 128>>>(x);
    seq_kernel<<<1, 32>>>(W2, b2);
    epi_kernel<<<(T_STEPS * 8) / 256, 256>>>(W3, b3, out);
}